// round 14
// baseline (speedup 1.0000x reference)
#include <cuda_runtime.h>
#include <cuda_fp16.h>
#include <cstdint>
#include <math.h>

#define N_NODES 50000
#define N_EDGES 800000
#define IN_FEAT 512
#define OUT_FEAT 128

#define LO_SCALE 2048.0f
#define LO_INV   (1.0f / 2048.0f)

// M split: tensor path rows [0, MT_ROWS), ffma path rows [MT_ROWS, N_NODES).
#define NT_BLOCKS 1106
#define NF_BLOCKS 457
#define NTOT_BLOCKS (NT_BLOCKS + NF_BLOCKS)   // 1563
#define MT_ROWS (NT_BLOCKS * 32)              // 35392

// Scratch buffers.
__device__ float  g_x[(size_t)N_NODES * OUT_FEAT];
__device__ int    g_row_ptr[N_NODES + 1];
// fp16 B fragments (m16n8k16): slot = s*16 + nbg, idx = slot*32 + lane;
// n = nbg*8 + (lane>>2), k = s*16 + 2*(lane&3);
// {f16x2 hiB(k,k+1), f16x2 hiB(k+8,k+9), f16x2 loB_s(k,k+1), f16x2 loB_s(k+8,k+9)}
// hiB = fp16(B), loB_s = fp16(2048*(B-hiB)).                          (256 KB)
__device__ uint4 g_Bf16[32 * 16 * 32];
// Raw fp32 weight copy for the ffma path.
__device__ float g_Wraw[IN_FEAT * OUT_FEAT];

__device__ __forceinline__ uint32_t h2_bits(__half2 h) { return *(uint32_t*)&h; }

// ---------------------------------------------------------------------------
// Kernel 1: row_ptr scatter + B fragment table + raw W copy (merged).
// ---------------------------------------------------------------------------
__global__ void prep_kernel(const int* __restrict__ rows,
                            const float* __restrict__ B) {
    const int t = blockIdx.x * blockDim.x + threadIdx.x;

    // ---- fp16 B fragments (first 16384 threads) ----
    if (t < 32 * 16 * 32) {
        const int lane = t & 31, nbg = (t >> 5) & 15, s = t >> 9;
        const int t4 = lane & 3, g = lane >> 2;
        const int n = nbg * 8 + g;
        const int k = s * 16 + 2 * t4;
        const float b0 = __ldg(&B[(size_t)(k + 0) * OUT_FEAT + n]);
        const float b1 = __ldg(&B[(size_t)(k + 1) * OUT_FEAT + n]);
        const float b8 = __ldg(&B[(size_t)(k + 8) * OUT_FEAT + n]);
        const float b9 = __ldg(&B[(size_t)(k + 9) * OUT_FEAT + n]);
        __half2 h01 = __floats2half2_rn(b0, b1);
        __half2 h89 = __floats2half2_rn(b8, b9);
        float2 f01 = __half22float2(h01);
        float2 f89 = __half22float2(h89);
        __half2 l01 = __floats2half2_rn((b0 - f01.x) * LO_SCALE, (b1 - f01.y) * LO_SCALE);
        __half2 l89 = __floats2half2_rn((b8 - f89.x) * LO_SCALE, (b9 - f89.y) * LO_SCALE);
        g_Bf16[t] = make_uint4(h2_bits(h01), h2_bits(h89), h2_bits(l01), h2_bits(l89));
    }
    // ---- raw W copy (first 16384 threads, float4 each) ----
    if (t < IN_FEAT * OUT_FEAT / 4)
        ((float4*)g_Wraw)[t] = ((const float4*)B)[t];

    // ---- row_ptr scatter ----
    const int e0 = t * 4;
    if (e0 >= N_EDGES) return;
    const int4 r4 = *(const int4*)&rows[e0];
    int prev = (t == 0) ? -1 : __ldg(&rows[e0 - 1]);
    int rv[4] = {r4.x, r4.y, r4.z, r4.w};
    #pragma unroll
    for (int j = 0; j < 4; ++j) {
        for (int r = prev + 1; r <= rv[j]; ++r) g_row_ptr[r] = e0 + j;
        prev = rv[j];
    }
    if (e0 + 4 == N_EDGES) {
        for (int r = prev + 1; r <= N_NODES; ++r) g_row_ptr[r] = N_EDGES;
    }
}

// ---------------------------------------------------------------------------
// Kernel 2: HYBRID GEMM  g_x[M,128] = feat[M,512] @ W[512,128]
// Bresenham-interleaved block split between two co-resident paths:
//   tensor path (R11): fp16 hi/scaled-lo, 3x m16n8k16 per k16, fp32 accum.
//   ffma path: exact fp32 SIMT, 32x128 tile, 4x8 microtile (idle FMA pipe).
// ---------------------------------------------------------------------------
#define KC 32
#define NCHUNK (IN_FEAT / KC)     // 16
#define NSTEP 32
#define AB_STRIDE 20              // f16x2 words per A row (16 + 4 pad)
#define KCF 16                    // ffma path K chunk
#define F_AS 36                   // As row stride (floats)
#define F_BS 136                  // Bs row stride (floats)
#define SMEM_WORDS 2944           // max(2560 tensor, 576+2176=2752 ffma)

#define MMA_F16(cc, aa, b0, b1)                                                \
    asm volatile(                                                              \
        "mma.sync.aligned.m16n8k16.row.col.f32.f16.f16.f32 "                   \
        "{%0,%1,%2,%3}, {%4,%5,%6,%7}, {%8,%9}, {%0,%1,%2,%3};"                \
        : "+f"((cc)[0]), "+f"((cc)[1]), "+f"((cc)[2]), "+f"((cc)[3])           \
        : "r"((aa)[0]), "r"((aa)[1]), "r"((aa)[2]), "r"((aa)[3]),              \
          "r"(b0), "r"(b1))

__global__ __launch_bounds__(128, 3) void gemm_hybrid_kernel(
    const float* __restrict__ A)   // feat [N_NODES, 512]
{
    __shared__ float smem[SMEM_WORDS];

    const int bid = blockIdx.x;
    const int tid = threadIdx.x;
    const int tBefore = (int)(((long long)bid * NT_BLOCKS) / NTOT_BLOCKS);
    const bool isTensor =
        ((((long long)(bid + 1) * NT_BLOCKS) / NTOT_BLOCKS) != tBefore);

    if (isTensor) {
        // ================= tensor path (R11, BM=32) =================
        uint32_t* sAh = (uint32_t*)smem;            // [2][640]
        uint32_t* sAl = (uint32_t*)smem + 1280;     // [2][640]

        const int wn   = tid >> 5;
        const int lane = tid & 31;
        const int g    = lane >> 2;
        const int t4   = lane & 3;
        const int m0   = tBefore * 32;   // all rows < MT_ROWS, always in-bounds

        const int fm[2] = { tid >> 3, 16 + (tid >> 3) };
        const int fk4 = tid & 7;

        float4 pf[2];
        auto ldgA = [&](int ch) {
            const int k0 = ch * KC;
            #pragma unroll
            for (int it = 0; it < 2; ++it)
                pf[it] = *(const float4*)&A[(size_t)(m0 + fm[it]) * IN_FEAT + k0 + fk4 * 4];
        };
        auto stsA = [&](int b) {
            #pragma unroll
            for (int it = 0; it < 2; ++it) {
                const float4 v = pf[it];
                __half2 h01 = __floats2half2_rn(v.x, v.y);
                __half2 h23 = __floats2half2_rn(v.z, v.w);
                float2 f01 = __half22float2(h01);
                float2 f23 = __half22float2(h23);
                __half2 l01 = __floats2half2_rn((v.x - f01.x) * LO_SCALE,
                                                (v.y - f01.y) * LO_SCALE);
                __half2 l23 = __floats2half2_rn((v.z - f23.x) * LO_SCALE,
                                                (v.w - f23.y) * LO_SCALE);
                const int w = b * 640 + fm[it] * AB_STRIDE + fk4 * 2;
                *(uint2*)&sAh[w] = make_uint2(h2_bits(h01), h2_bits(h23));
                *(uint2*)&sAl[w] = make_uint2(h2_bits(l01), h2_bits(l23));
            }
        };

        uint4 bf[2][4];
        auto ldB = [&](int s, int p) {
            #pragma unroll
            for (int nb = 0; nb < 4; ++nb)
                bf[p][nb] = __ldg(&g_Bf16[(size_t)(s * 16 + wn * 4 + nb) * 32 + lane]);
        };

        float c[2][4][4], c2[2][4][4];
        #pragma unroll
        for (int i = 0; i < 2; i++)
            #pragma unroll
            for (int j = 0; j < 4; j++)
                #pragma unroll
                for (int q = 0; q < 4; q++) { c[i][j][q] = 0.0f; c2[i][j][q] = 0.0f; }

        ldB(0, 0);
        ldgA(0);
        stsA(0);

        for (int ch = 0; ch < NCHUNK; ++ch) {
            const int buf = ch & 1;
            if (ch + 1 < NCHUNK) ldgA(ch + 1);
            __syncthreads();

            const uint32_t* ahp = sAh + buf * 640;
            const uint32_t* alp = sAl + buf * 640;

            #pragma unroll
            for (int ks2 = 0; ks2 < 2; ++ks2) {
                const int s = ch * 2 + ks2;
                const int p = s & 1;
                if (s + 1 < NSTEP) ldB(s + 1, p ^ 1);

                #pragma unroll
                for (int mb = 0; mb < 2; ++mb) {
                    const int r0 = mb * 16 + g;
                    const int w0 = r0 * AB_STRIDE + ks2 * 8 + t4;
                    const int w8 = (r0 + 8) * AB_STRIDE + ks2 * 8 + t4;
                    uint32_t ah[4], al[4];
                    ah[0] = ahp[w0];     ah[1] = ahp[w8];
                    ah[2] = ahp[w0 + 4]; ah[3] = ahp[w8 + 4];
                    al[0] = alp[w0];     al[1] = alp[w8];
                    al[2] = alp[w0 + 4]; al[3] = alp[w8 + 4];

                    #pragma unroll
                    for (int nb = 0; nb < 4; ++nb) {
                        MMA_F16(c [mb][nb], ah, bf[p][nb].x, bf[p][nb].y);
                        MMA_F16(c2[mb][nb], al, bf[p][nb].x, bf[p][nb].y);
                        MMA_F16(c2[mb][nb], ah, bf[p][nb].z, bf[p][nb].w);
                    }
                }
            }
            if (ch + 1 < NCHUNK) stsA(buf ^ 1);
        }

        #pragma unroll
        for (int mb = 0; mb < 2; ++mb)
            #pragma unroll
            for (int half = 0; half < 2; ++half) {
                const int row = m0 + mb * 16 + g + half * 8;
                #pragma unroll
                for (int nb = 0; nb < 4; ++nb) {
                    const int col = wn * 32 + nb * 8 + 2 * t4;
                    float2 v = make_float2(
                        fmaf(c2[mb][nb][2 * half],     LO_INV, c[mb][nb][2 * half]),
                        fmaf(c2[mb][nb][2 * half + 1], LO_INV, c[mb][nb][2 * half + 1]));
                    *(float2*)&g_x[(size_t)row * OUT_FEAT + col] = v;
                }
            }
    } else {
        // ================= ffma path (exact fp32, 32x128 tile) =================
        float* As = smem;               // As[k][m], 16 x 36
        float* Bs = smem + 16 * F_AS;   // Bs[k][n], 16 x 136

        const int fIdx = bid - tBefore;            // 0..NF_BLOCKS-1
        const int m0   = MT_ROWS + fIdx * 32;
        const int tx   = tid & 15;   // n microtile (cols tx + 16j)
        const int ty   = tid >> 4;   // m microtile (rows ty*4..+3)

        const int aRow = tid >> 2;          // 0..31
        const int aK4  = tid & 3;           // float4 along k

        float acc[4][8];
        #pragma unroll
        for (int i = 0; i < 4; ++i)
            #pragma unroll
            for (int j = 0; j < 8; ++j) acc[i][j] = 0.0f;

        for (int ch = 0; ch < IN_FEAT / KCF; ++ch) {   // 32 chunks of k16
            const int k0 = ch * KCF;
            // load chunk tiles into registers
            float4 pfA = make_float4(0.f, 0.f, 0.f, 0.f);
            {
                const int gm = m0 + aRow;
                if (gm < N_NODES)
                    pfA = *(const float4*)&A[(size_t)gm * IN_FEAT + k0 + aK4 * 4];
            }
            float4 pfB[4];
            #pragma unroll
            for (int j = 0; j < 4; ++j) {
                const int slot = tid + j * 128;      // 0..511
                const int kk = slot >> 5, n4 = slot & 31;
                pfB[j] = *(const float4*)&g_Wraw[(size_t)(k0 + kk) * OUT_FEAT + n4 * 4];
            }
            __syncthreads();   // previous chunk's readers done
            As[(aK4 * 4 + 0) * F_AS + aRow] = pfA.x;
            As[(aK4 * 4 + 1) * F_AS + aRow] = pfA.y;
            As[(aK4 * 4 + 2) * F_AS + aRow] = pfA.z;
            As[(aK4 * 4 + 3) * F_AS + aRow] = pfA.w;
            #pragma unroll
            for (int j = 0; j < 4; ++j) {
                const int slot = tid + j * 128;
                const int kk = slot >> 5, n4 = slot & 31;
                *(float4*)&Bs[kk * F_BS + n4 * 4] = pfB[j];
            }
            __syncthreads();

            // compute with per-k fragment prefetch
            float rm[2][4], rn[2][8];
            #pragma unroll
            for (int i = 0; i < 4; ++i) rm[0][i] = As[0 * F_AS + ty * 4 + i];
            #pragma unroll
            for (int j = 0; j < 8; ++j) rn[0][j] = Bs[0 * F_BS + tx + 16 * j];
            #pragma unroll
            for (int k = 0; k < KCF; ++k) {
                const int cur = k & 1, nxt = cur ^ 1;
                if (k < KCF - 1) {
                    #pragma unroll
                    for (int i = 0; i < 4; ++i) rm[nxt][i] = As[(k + 1) * F_AS + ty * 4 + i];
                    #pragma unroll
                    for (int j = 0; j < 8; ++j) rn[nxt][j] = Bs[(k + 1) * F_BS + tx + 16 * j];
                }
                #pragma unroll
                for (int i = 0; i < 4; ++i)
                    #pragma unroll
                    for (int j = 0; j < 8; ++j)
                        acc[i][j] = fmaf(rm[cur][i], rn[cur][j], acc[i][j]);
            }
        }

        #pragma unroll
        for (int i = 0; i < 4; ++i) {
            const int row = m0 + ty * 4 + i;
            if (row < N_NODES) {
                #pragma unroll
                for (int j = 0; j < 8; ++j)
                    g_x[(size_t)row * OUT_FEAT + tx + 16 * j] = acc[i][j];
            }
        }
    }
}

// ---------------------------------------------------------------------------
// Kernel 3: SpMM (warp per row, no atomics) + multispike epilogue.
// At the LTS cap with compulsory traffic — unchanged.
// ---------------------------------------------------------------------------
__device__ __forceinline__ float multispike(float x) {
    return floorf(fminf(fmaxf(4.0f * x, 0.0f), 4.0f) + 0.5f) * 0.25f;
}

__global__ __launch_bounds__(256) void spmm_kernel(
    const int*   __restrict__ cols,
    const float* __restrict__ ew,
    float*       __restrict__ out)
{
    const int warp = (blockIdx.x * blockDim.x + threadIdx.x) >> 5;
    const int lane = threadIdx.x & 31;
    if (warp >= N_NODES) return;

    const int e0 = g_row_ptr[warp];
    const int e1 = g_row_ptr[warp + 1];

    float4 acc = make_float4(0.f, 0.f, 0.f, 0.f);
    const int fo = lane * 4;

    int e = e0;
    for (; e + 3 < e1; e += 4) {
        int   cc[4];
        float ww[4];
        #pragma unroll
        for (int j = 0; j < 4; ++j) { cc[j] = __ldg(&cols[e + j]); ww[j] = __ldg(&ew[e + j]); }
        #pragma unroll
        for (int j = 0; j < 4; ++j) {
            const float4 v = *(const float4*)&g_x[(size_t)cc[j] * OUT_FEAT + fo];
            acc.x = fmaf(ww[j], v.x, acc.x); acc.y = fmaf(ww[j], v.y, acc.y);
            acc.z = fmaf(ww[j], v.z, acc.z); acc.w = fmaf(ww[j], v.w, acc.w);
        }
    }
    for (; e < e1; ++e) {
        const int   c0 = __ldg(&cols[e]);
        const float w0 = __ldg(&ew[e]);
        const float4 v0 = *(const float4*)&g_x[(size_t)c0 * OUT_FEAT + fo];
        acc.x = fmaf(w0, v0.x, acc.x); acc.y = fmaf(w0, v0.y, acc.y);
        acc.z = fmaf(w0, v0.z, acc.z); acc.w = fmaf(w0, v0.w, acc.w);
    }

    acc.x = multispike(acc.x);
    acc.y = multispike(acc.y);
    acc.z = multispike(acc.z);
    acc.w = multispike(acc.w);
    *(float4*)&out[(size_t)warp * OUT_FEAT + fo] = acc;
}

// ---------------------------------------------------------------------------
extern "C" void kernel_launch(void* const* d_in, const int* in_sizes, int n_in,
                              void* d_out, int out_size) {
    const float* feat   = (const float*)d_in[0];
    const float* weight = (const float*)d_in[1];
    const int*   rows   = (const int*)d_in[2];
    const int*   cols   = (const int*)d_in[3];
    const float* ew     = (const float*)d_in[4];
    float* out = (float*)d_out;

    prep_kernel<<<(N_EDGES / 4 + 256) / 256, 256>>>(rows, weight);
    gemm_hybrid_kernel<<<NTOT_BLOCKS, 128>>>(feat);
    spmm_kernel<<<(N_NODES * 32 + 255) / 256, 256>>>(cols, ew, out);
}

// round 15
// speedup vs baseline: 1.6090x; 1.6090x over previous
#include <cuda_runtime.h>
#include <cuda_fp16.h>
#include <cstdint>
#include <math.h>

#define N_NODES 50000
#define N_EDGES 800000
#define IN_FEAT 512
#define OUT_FEAT 128

#define LO_SCALE 2048.0f
#define LO_INV   (1.0f / 2048.0f)

// Scratch buffers.
__device__ float  g_x[(size_t)N_NODES * OUT_FEAT];
__device__ int    g_row_ptr[N_NODES + 1];
// fp16 B fragments (m16n8k16): slot = s*16 + nbg (s 0..31, nbg 0..15),
// idx = slot*32 + lane; n = nbg*8 + (lane>>2), k = s*16 + 2*(lane&3);
// {f16x2 hiB(k,k+1), f16x2 hiB(k+8,k+9), f16x2 loB_s(k,k+1), f16x2 loB_s(k+8,k+9)}
// hiB = fp16(B), loB_s = fp16(2048*(B-hiB)).                          (256 KB)
__device__ uint4 g_Bf16[32 * 16 * 32];

__device__ __forceinline__ uint32_t h2_bits(__half2 h) { return *(uint32_t*)&h; }

// ---------------------------------------------------------------------------
// Kernel 1: row_ptr scatter + B fragment table (merged).
// ---------------------------------------------------------------------------
__global__ void prep_kernel(const int* __restrict__ rows,
                            const float* __restrict__ B) {
    const int t = blockIdx.x * blockDim.x + threadIdx.x;

    if (t < 32 * 16 * 32) {
        const int lane = t & 31, nbg = (t >> 5) & 15, s = t >> 9;
        const int t4 = lane & 3, g = lane >> 2;
        const int n = nbg * 8 + g;
        const int k = s * 16 + 2 * t4;
        const float b0 = __ldg(&B[(size_t)(k + 0) * OUT_FEAT + n]);
        const float b1 = __ldg(&B[(size_t)(k + 1) * OUT_FEAT + n]);
        const float b8 = __ldg(&B[(size_t)(k + 8) * OUT_FEAT + n]);
        const float b9 = __ldg(&B[(size_t)(k + 9) * OUT_FEAT + n]);
        __half2 h01 = __floats2half2_rn(b0, b1);
        __half2 h89 = __floats2half2_rn(b8, b9);
        float2 f01 = __half22float2(h01);
        float2 f89 = __half22float2(h89);
        __half2 l01 = __floats2half2_rn((b0 - f01.x) * LO_SCALE, (b1 - f01.y) * LO_SCALE);
        __half2 l89 = __floats2half2_rn((b8 - f89.x) * LO_SCALE, (b9 - f89.y) * LO_SCALE);
        g_Bf16[t] = make_uint4(h2_bits(h01), h2_bits(h89), h2_bits(l01), h2_bits(l89));
    }

    const int e0 = t * 4;
    if (e0 >= N_EDGES) return;
    const int4 r4 = *(const int4*)&rows[e0];
    int prev = (t == 0) ? -1 : __ldg(&rows[e0 - 1]);
    int rv[4] = {r4.x, r4.y, r4.z, r4.w};
    #pragma unroll
    for (int j = 0; j < 4; ++j) {
        for (int r = prev + 1; r <= rv[j]; ++r) g_row_ptr[r] = e0 + j;
        prev = rv[j];
    }
    if (e0 + 4 == N_EDGES) {
        for (int r = prev + 1; r <= N_NODES; ++r) g_row_ptr[r] = N_EDGES;
    }
}

// ---------------------------------------------------------------------------
// Kernel 2: GEMM  g_x[M,128] = feat[M,512] @ W[512,128]
// Per k16 step (R11 scheme, accumulator experiment):
//   c  (fp32 accum) += hiA*hiB              1x m16n8k16 f32.f16.f16.f32
//   c2 (fp16 accum) += loA_s*hiB + hiA*loB_s 2x m16n8k16 f16.f16.f16.f16
//   final = c + float(c2)/2048
// fp16 accum of c2 is safe: |c2| ~ O(1) (normal range), rounding noise
// after /2048 is ~5e-7 relative — invisible under quantization.
// CTA 32(M) x 128(N), 128 threads, warp tile 32x32; B reg-prefetched 1 step.
// ---------------------------------------------------------------------------
#define BM 32
#define KC 32
#define NCHUNK (IN_FEAT / KC)     // 16
#define NSTEP 32
#define AB_STRIDE 20              // f16x2 words per A row (16 + 4 pad)

#define MMA_F16_F32(cc, aa, b0, b1)                                            \
    asm volatile(                                                              \
        "mma.sync.aligned.m16n8k16.row.col.f32.f16.f16.f32 "                   \
        "{%0,%1,%2,%3}, {%4,%5,%6,%7}, {%8,%9}, {%0,%1,%2,%3};"                \
        : "+f"((cc)[0]), "+f"((cc)[1]), "+f"((cc)[2]), "+f"((cc)[3])           \
        : "r"((aa)[0]), "r"((aa)[1]), "r"((aa)[2]), "r"((aa)[3]),              \
          "r"(b0), "r"(b1))

// fp16-accumulate variant: C/D are 2 regs of packed f16x2.
#define MMA_F16_F16(cc, aa, b0, b1)                                            \
    asm volatile(                                                              \
        "mma.sync.aligned.m16n8k16.row.col.f16.f16.f16.f16 "                   \
        "{%0,%1}, {%2,%3,%4,%5}, {%6,%7}, {%0,%1};"                            \
        : "+r"((cc)[0]), "+r"((cc)[1])                                         \
        : "r"((aa)[0]), "r"((aa)[1]), "r"((aa)[2]), "r"((aa)[3]),              \
          "r"(b0), "r"(b1))

__global__ __launch_bounds__(128, 4) void gemm_mma_kernel(
    const float* __restrict__ A)   // feat [N_NODES, 512]
{
    __shared__ uint32_t sAh[2][BM * AB_STRIDE];   // fp16x2 hi
    __shared__ uint32_t sAl[2][BM * AB_STRIDE];   // fp16x2 scaled lo

    const int tid  = threadIdx.x;
    const int wn   = tid >> 5;
    const int lane = tid & 31;
    const int g    = lane >> 2;
    const int t4   = lane & 3;
    const int m0   = blockIdx.x * BM;

    const int fm[2] = { tid >> 3, 16 + (tid >> 3) };
    const int fk4 = tid & 7;

    float4 pf[2];
    auto ldgA = [&](int ch) {
        const int k0 = ch * KC;
        #pragma unroll
        for (int it = 0; it < 2; ++it) {
            const int gm = m0 + fm[it];
            pf[it] = make_float4(0.f, 0.f, 0.f, 0.f);
            if (gm < N_NODES)
                pf[it] = *(const float4*)&A[(size_t)gm * IN_FEAT + k0 + fk4 * 4];
        }
    };
    auto stsA = [&](int b) {
        #pragma unroll
        for (int it = 0; it < 2; ++it) {
            const float4 v = pf[it];
            __half2 h01 = __floats2half2_rn(v.x, v.y);
            __half2 h23 = __floats2half2_rn(v.z, v.w);
            float2 f01 = __half22float2(h01);
            float2 f23 = __half22float2(h23);
            __half2 l01 = __floats2half2_rn((v.x - f01.x) * LO_SCALE,
                                            (v.y - f01.y) * LO_SCALE);
            __half2 l23 = __floats2half2_rn((v.z - f23.x) * LO_SCALE,
                                            (v.w - f23.y) * LO_SCALE);
            const int w = fm[it] * AB_STRIDE + fk4 * 2;
            *(uint2*)&sAh[b][w] = make_uint2(h2_bits(h01), h2_bits(h23));
            *(uint2*)&sAl[b][w] = make_uint2(h2_bits(l01), h2_bits(l23));
        }
    };

    uint4 bf[2][4];
    auto ldB = [&](int s, int p) {
        #pragma unroll
        for (int nb = 0; nb < 4; ++nb)
            bf[p][nb] = __ldg(&g_Bf16[(size_t)(s * 16 + wn * 4 + nb) * 32 + lane]);
    };

    float    c [2][4][4];
    uint32_t c2[2][4][2];          // packed f16x2 accumulators
    #pragma unroll
    for (int i = 0; i < 2; i++)
        #pragma unroll
        for (int j = 0; j < 4; j++) {
            #pragma unroll
            for (int q = 0; q < 4; q++) c[i][j][q] = 0.0f;
            c2[i][j][0] = 0u; c2[i][j][1] = 0u;
        }

    ldB(0, 0);
    ldgA(0);
    stsA(0);

    for (int ch = 0; ch < NCHUNK; ++ch) {
        const int buf = ch & 1;
        if (ch + 1 < NCHUNK) ldgA(ch + 1);
        __syncthreads();

        const uint32_t* ahp = sAh[buf];
        const uint32_t* alp = sAl[buf];

        #pragma unroll
        for (int ks2 = 0; ks2 < 2; ++ks2) {
            const int s = ch * 2 + ks2;
            const int p = s & 1;
            if (s + 1 < NSTEP) ldB(s + 1, p ^ 1);   // prefetch next step's B

            #pragma unroll
            for (int mb = 0; mb < 2; ++mb) {
                const int r0 = mb * 16 + g;
                const int w0 = r0 * AB_STRIDE + ks2 * 8 + t4;
                const int w8 = (r0 + 8) * AB_STRIDE + ks2 * 8 + t4;
                uint32_t ah[4], al[4];
                ah[0] = ahp[w0];     ah[1] = ahp[w8];
                ah[2] = ahp[w0 + 4]; ah[3] = ahp[w8 + 4];
                al[0] = alp[w0];     al[1] = alp[w8];
                al[2] = alp[w0 + 4]; al[3] = alp[w8 + 4];

                #pragma unroll
                for (int nb = 0; nb < 4; ++nb) {
                    MMA_F16_F32(c [mb][nb], ah, bf[p][nb].x, bf[p][nb].y); // hi*hi (fp32 acc)
                    MMA_F16_F16(c2[mb][nb], al, bf[p][nb].x, bf[p][nb].y); // loA_s*hiB (fp16 acc)
                    MMA_F16_F16(c2[mb][nb], ah, bf[p][nb].z, bf[p][nb].w); // hiA*loB_s (fp16 acc)
                }
            }
        }

        if (ch + 1 < NCHUNK) stsA(buf ^ 1);
    }

    // ---- epilogue: final = c + float(c2)/2048 ----
    #pragma unroll
    for (int mb = 0; mb < 2; ++mb) {
        #pragma unroll
        for (int half = 0; half < 2; ++half) {
            const int row = m0 + mb * 16 + g + half * 8;
            if (row < N_NODES) {
                #pragma unroll
                for (int nb = 0; nb < 4; ++nb) {
                    const int col = wn * 32 + nb * 8 + 2 * t4;
                    const __half2 h2v = *(__half2*)&c2[mb][nb][half];
                    const float2 corr = __half22float2(h2v);
                    float2 v = make_float2(
                        fmaf(corr.x, LO_INV, c[mb][nb][2 * half]),
                        fmaf(corr.y, LO_INV, c[mb][nb][2 * half + 1]));
                    *(float2*)&g_x[(size_t)row * OUT_FEAT + col] = v;
                }
            }
        }
    }
}

// ---------------------------------------------------------------------------
// Kernel 3: SpMM (warp per row, no atomics) + multispike epilogue.
// At the LTS cap with compulsory traffic — unchanged.
// ---------------------------------------------------------------------------
__device__ __forceinline__ float multispike(float x) {
    return floorf(fminf(fmaxf(4.0f * x, 0.0f), 4.0f) + 0.5f) * 0.25f;
}

__global__ __launch_bounds__(256) void spmm_kernel(
    const int*   __restrict__ cols,
    const float* __restrict__ ew,
    float*       __restrict__ out)
{
    const int warp = (blockIdx.x * blockDim.x + threadIdx.x) >> 5;
    const int lane = threadIdx.x & 31;
    if (warp >= N_NODES) return;

    const int e0 = g_row_ptr[warp];
    const int e1 = g_row_ptr[warp + 1];

    float4 acc = make_float4(0.f, 0.f, 0.f, 0.f);
    const int fo = lane * 4;

    int e = e0;
    for (; e + 3 < e1; e += 4) {
        int   cc[4];
        float ww[4];
        #pragma unroll
        for (int j = 0; j < 4; ++j) { cc[j] = __ldg(&cols[e + j]); ww[j] = __ldg(&ew[e + j]); }
        #pragma unroll
        for (int j = 0; j < 4; ++j) {
            const float4 v = *(const float4*)&g_x[(size_t)cc[j] * OUT_FEAT + fo];
            acc.x = fmaf(ww[j], v.x, acc.x); acc.y = fmaf(ww[j], v.y, acc.y);
            acc.z = fmaf(ww[j], v.z, acc.z); acc.w = fmaf(ww[j], v.w, acc.w);
        }
    }
    for (; e < e1; ++e) {
        const int   c0 = __ldg(&cols[e]);
        const float w0 = __ldg(&ew[e]);
        const float4 v0 = *(const float4*)&g_x[(size_t)c0 * OUT_FEAT + fo];
        acc.x = fmaf(w0, v0.x, acc.x); acc.y = fmaf(w0, v0.y, acc.y);
        acc.z = fmaf(w0, v0.z, acc.z); acc.w = fmaf(w0, v0.w, acc.w);
    }

    acc.x = multispike(acc.x);
    acc.y = multispike(acc.y);
    acc.z = multispike(acc.z);
    acc.w = multispike(acc.w);
    *(float4*)&out[(size_t)warp * OUT_FEAT + fo] = acc;
}

// ---------------------------------------------------------------------------
extern "C" void kernel_launch(void* const* d_in, const int* in_sizes, int n_in,
                              void* d_out, int out_size) {
    const float* feat   = (const float*)d_in[0];
    const float* weight = (const float*)d_in[1];
    const int*   rows   = (const int*)d_in[2];
    const int*   cols   = (const int*)d_in[3];
    const float* ew     = (const float*)d_in[4];
    float* out = (float*)d_out;

    prep_kernel<<<(N_EDGES / 4 + 256) / 256, 256>>>(rows, weight);
    gemm_mma_kernel<<<(N_NODES + BM - 1) / BM, 128>>>(feat);
    spmm_kernel<<<(N_NODES * 32 + 255) / 256, 256>>>(cols, ew, out);
}

// round 16
// speedup vs baseline: 1.6334x; 1.0152x over previous
#include <cuda_runtime.h>
#include <cuda_fp16.h>
#include <cstdint>
#include <math.h>

#define N_NODES 50000
#define N_EDGES 800000
#define IN_FEAT 512
#define OUT_FEAT 128

#define LO_SCALE 2048.0f
#define LO_INV   (1.0f / 2048.0f)

// Scratch buffers.
__device__ float  g_x[(size_t)N_NODES * OUT_FEAT];
__device__ int    g_row_ptr[N_NODES + 1];
// fp16 B fragments (m16n8k16): slot = s*16 + nbg (s 0..31, nbg 0..15),
// idx = slot*32 + lane; n = nbg*8 + (lane>>2), k = s*16 + 2*(lane&3);
// {f16x2 hiB(k,k+1), f16x2 hiB(k+8,k+9), f16x2 loB_s(k,k+1), f16x2 loB_s(k+8,k+9)}
// hiB = fp16(B), loB_s = fp16(2048*(B-hiB)).                          (256 KB)
__device__ uint4 g_Bf16[32 * 16 * 32];

__device__ __forceinline__ uint32_t h2_bits(__half2 h) { return *(uint32_t*)&h; }

// ---------------------------------------------------------------------------
// Kernel 1: row_ptr scatter + B fragment table (merged).
// ---------------------------------------------------------------------------
__global__ void prep_kernel(const int* __restrict__ rows,
                            const float* __restrict__ B) {
    const int t = blockIdx.x * blockDim.x + threadIdx.x;

    if (t < 32 * 16 * 32) {
        const int lane = t & 31, nbg = (t >> 5) & 15, s = t >> 9;
        const int t4 = lane & 3, g = lane >> 2;
        const int n = nbg * 8 + g;
        const int k = s * 16 + 2 * t4;
        const float b0 = __ldg(&B[(size_t)(k + 0) * OUT_FEAT + n]);
        const float b1 = __ldg(&B[(size_t)(k + 1) * OUT_FEAT + n]);
        const float b8 = __ldg(&B[(size_t)(k + 8) * OUT_FEAT + n]);
        const float b9 = __ldg(&B[(size_t)(k + 9) * OUT_FEAT + n]);
        __half2 h01 = __floats2half2_rn(b0, b1);
        __half2 h89 = __floats2half2_rn(b8, b9);
        float2 f01 = __half22float2(h01);
        float2 f89 = __half22float2(h89);
        __half2 l01 = __floats2half2_rn((b0 - f01.x) * LO_SCALE, (b1 - f01.y) * LO_SCALE);
        __half2 l89 = __floats2half2_rn((b8 - f89.x) * LO_SCALE, (b9 - f89.y) * LO_SCALE);
        g_Bf16[t] = make_uint4(h2_bits(h01), h2_bits(h89), h2_bits(l01), h2_bits(l89));
    }

    const int e0 = t * 4;
    if (e0 >= N_EDGES) return;
    const int4 r4 = *(const int4*)&rows[e0];
    int prev = (t == 0) ? -1 : __ldg(&rows[e0 - 1]);
    int rv[4] = {r4.x, r4.y, r4.z, r4.w};
    #pragma unroll
    for (int j = 0; j < 4; ++j) {
        for (int r = prev + 1; r <= rv[j]; ++r) g_row_ptr[r] = e0 + j;
        prev = rv[j];
    }
    if (e0 + 4 == N_EDGES) {
        for (int r = prev + 1; r <= N_NODES; ++r) g_row_ptr[r] = N_EDGES;
    }
}

// ---------------------------------------------------------------------------
// Kernel 2: GEMM  g_x[M,128] = feat[M,512] @ W[512,128]
// R15 scheme (hi*hi fp32-acc + scaled-lo corrections fp16-acc), but A is
// stored in SMEM in MMA FRAGMENT ORDER: per (ks2, mb) slot, lane ℓ's uint4
// is exactly its {a0,a1,a2,a3} operand. Fragment load = 1 LDS.128 (ah) +
// 1 LDS.128 (al) per mb-step instead of 16 scalar LDS. Same values, same
// MMA order -> rel_err must be bit-identical to R15.
// CTA 32(M) x 128(N), 128 threads, warp tile 32x32; B reg-prefetched 1 step.
// ---------------------------------------------------------------------------
#define BM 32
#define KC 32
#define NCHUNK (IN_FEAT / KC)     // 16
#define NSTEP 32
// fragment-ordered A: [buf][slot = ks2*2+mb][lane] -> uint4 (512 u32 per buf)
#define AFRAG_U32 512

#define MMA_F16_F32(cc, aa, b0, b1)                                            \
    asm volatile(                                                              \
        "mma.sync.aligned.m16n8k16.row.col.f32.f16.f16.f32 "                   \
        "{%0,%1,%2,%3}, {%4,%5,%6,%7}, {%8,%9}, {%0,%1,%2,%3};"                \
        : "+f"((cc)[0]), "+f"((cc)[1]), "+f"((cc)[2]), "+f"((cc)[3])           \
        : "r"((aa)[0]), "r"((aa)[1]), "r"((aa)[2]), "r"((aa)[3]),              \
          "r"(b0), "r"(b1))

#define MMA_F16_F16(cc, aa, b0, b1)                                            \
    asm volatile(                                                              \
        "mma.sync.aligned.m16n8k16.row.col.f16.f16.f16.f16 "                   \
        "{%0,%1}, {%2,%3,%4,%5}, {%6,%7}, {%0,%1};"                            \
        : "+r"((cc)[0]), "+r"((cc)[1])                                         \
        : "r"((aa)[0]), "r"((aa)[1]), "r"((aa)[2]), "r"((aa)[3]),              \
          "r"(b0), "r"(b1))

__global__ __launch_bounds__(128, 4) void gemm_mma_kernel(
    const float* __restrict__ A)   // feat [N_NODES, 512]
{
    __shared__ uint32_t sAh[2][AFRAG_U32];   // fragment-ordered fp16x2 hi
    __shared__ uint32_t sAl[2][AFRAG_U32];   // fragment-ordered fp16x2 scaled lo

    const int tid  = threadIdx.x;
    const int wn   = tid >> 5;
    const int lane = tid & 31;
    const int m0   = blockIdx.x * BM;

    // A fill mapping: thread owns rows {tid>>3, 16+(tid>>3)}, k4 = tid&7.
    const int fm[2] = { tid >> 3, 16 + (tid >> 3) };
    const int fk4 = tid & 7;

    float4 pf[2];
    auto ldgA = [&](int ch) {
        const int k0 = ch * KC;
        #pragma unroll
        for (int it = 0; it < 2; ++it) {
            const int gm = m0 + fm[it];
            pf[it] = make_float4(0.f, 0.f, 0.f, 0.f);
            if (gm < N_NODES)
                pf[it] = *(const float4*)&A[(size_t)gm * IN_FEAT + k0 + fk4 * 4];
        }
    };
    // convert + scatter into fragment order
    auto stsA = [&](int b) {
        #pragma unroll
        for (int it = 0; it < 2; ++it) {
            const int row = fm[it];
            const int mb  = row >> 4;
            const int hi8 = (row >> 3) & 1;
            const int fl  = (row & 7) * 4;   // + t4
            const float4 v = pf[it];
            __half2 h01 = __floats2half2_rn(v.x, v.y);
            __half2 h23 = __floats2half2_rn(v.z, v.w);
            float2 f01 = __half22float2(h01);
            float2 f23 = __half22float2(h23);
            __half2 l01 = __floats2half2_rn((v.x - f01.x) * LO_SCALE,
                                            (v.y - f01.y) * LO_SCALE);
            __half2 l23 = __floats2half2_rn((v.z - f23.x) * LO_SCALE,
                                            (v.w - f23.y) * LO_SCALE);
            // word j covers k = 4*fk4 + 2*j  (j = 0, 1)
            #pragma unroll
            for (int j = 0; j < 2; ++j) {
                const int k   = 4 * fk4 + 2 * j;
                const int ks2 = k >> 4;
                const int kk  = k & 15;
                const int kh  = (kk >= 8) ? 1 : 0;
                const int t4w = (kk >> 1) & 3;
                const int reg = hi8 | (kh << 1);
                const int wi  = ((ks2 * 2 + mb) * 32 + fl + t4w) * 4 + reg;
                sAh[b][wi] = (j == 0) ? h2_bits(h01) : h2_bits(h23);
                sAl[b][wi] = (j == 0) ? h2_bits(l01) : h2_bits(l23);
            }
        }
    };

    uint4 bf[2][4];
    auto ldB = [&](int s, int p) {
        #pragma unroll
        for (int nb = 0; nb < 4; ++nb)
            bf[p][nb] = __ldg(&g_Bf16[(size_t)(s * 16 + wn * 4 + nb) * 32 + lane]);
    };

    float    c [2][4][4];
    uint32_t c2[2][4][2];          // packed f16x2 accumulators
    #pragma unroll
    for (int i = 0; i < 2; i++)
        #pragma unroll
        for (int j = 0; j < 4; j++) {
            #pragma unroll
            for (int q = 0; q < 4; q++) c[i][j][q] = 0.0f;
            c2[i][j][0] = 0u; c2[i][j][1] = 0u;
        }

    ldB(0, 0);
    ldgA(0);
    stsA(0);

    for (int ch = 0; ch < NCHUNK; ++ch) {
        const int buf = ch & 1;
        if (ch + 1 < NCHUNK) ldgA(ch + 1);
        __syncthreads();

        #pragma unroll
        for (int ks2 = 0; ks2 < 2; ++ks2) {
            const int s = ch * 2 + ks2;
            const int p = s & 1;
            if (s + 1 < NSTEP) ldB(s + 1, p ^ 1);   // prefetch next step's B

            #pragma unroll
            for (int mb = 0; mb < 2; ++mb) {
                const int base = ((ks2 * 2 + mb) * 32 + lane) * 4;
                const uint4 ah4 = *(const uint4*)&sAh[buf][base];
                const uint4 al4 = *(const uint4*)&sAl[buf][base];
                uint32_t ah[4] = { ah4.x, ah4.y, ah4.z, ah4.w };
                uint32_t al[4] = { al4.x, al4.y, al4.z, al4.w };

                #pragma unroll
                for (int nb = 0; nb < 4; ++nb) {
                    MMA_F16_F32(c [mb][nb], ah, bf[p][nb].x, bf[p][nb].y); // hi*hi
                    MMA_F16_F16(c2[mb][nb], al, bf[p][nb].x, bf[p][nb].y); // loA_s*hiB
                    MMA_F16_F16(c2[mb][nb], ah, bf[p][nb].z, bf[p][nb].w); // hiA*loB_s
                }
            }
        }

        if (ch + 1 < NCHUNK) stsA(buf ^ 1);
    }

    // ---- epilogue: final = c + float(c2)/2048 ----
    const int g  = lane >> 2;
    const int t4 = lane & 3;
    #pragma unroll
    for (int mb = 0; mb < 2; ++mb) {
        #pragma unroll
        for (int half = 0; half < 2; ++half) {
            const int row = m0 + mb * 16 + g + half * 8;
            if (row < N_NODES) {
                #pragma unroll
                for (int nb = 0; nb < 4; ++nb) {
                    const int col = wn * 32 + nb * 8 + 2 * t4;
                    const __half2 h2v = *(__half2*)&c2[mb][nb][half];
                    const float2 corr = __half22float2(h2v);
                    float2 v = make_float2(
                        fmaf(corr.x, LO_INV, c[mb][nb][2 * half]),
                        fmaf(corr.y, LO_INV, c[mb][nb][2 * half + 1]));
                    *(float2*)&g_x[(size_t)row * OUT_FEAT + col] = v;
                }
            }
        }
    }
}

// ---------------------------------------------------------------------------
// Kernel 3: SpMM (warp per row, no atomics) + multispike epilogue.
// At the LTS cap with compulsory traffic — unchanged.
// ---------------------------------------------------------------------------
__device__ __forceinline__ float multispike(float x) {
    return floorf(fminf(fmaxf(4.0f * x, 0.0f), 4.0f) + 0.5f) * 0.25f;
}

__global__ __launch_bounds__(256) void spmm_kernel(
    const int*   __restrict__ cols,
    const float* __restrict__ ew,
    float*       __restrict__ out)
{
    const int warp = (blockIdx.x * blockDim.x + threadIdx.x) >> 5;
    const int lane = threadIdx.x & 31;
    if (warp >= N_NODES) return;

    const int e0 = g_row_ptr[warp];
    const int e1 = g_row_ptr[warp + 1];

    float4 acc = make_float4(0.f, 0.f, 0.f, 0.f);
    const int fo = lane * 4;

    int e = e0;
    for (; e + 3 < e1; e += 4) {
        int   cc[4];
        float ww[4];
        #pragma unroll
        for (int j = 0; j < 4; ++j) { cc[j] = __ldg(&cols[e + j]); ww[j] = __ldg(&ew[e + j]); }
        #pragma unroll
        for (int j = 0; j < 4; ++j) {
            const float4 v = *(const float4*)&g_x[(size_t)cc[j] * OUT_FEAT + fo];
            acc.x = fmaf(ww[j], v.x, acc.x); acc.y = fmaf(ww[j], v.y, acc.y);
            acc.z = fmaf(ww[j], v.z, acc.z); acc.w = fmaf(ww[j], v.w, acc.w);
        }
    }
    for (; e < e1; ++e) {
        const int   c0 = __ldg(&cols[e]);
        const float w0 = __ldg(&ew[e]);
        const float4 v0 = *(const float4*)&g_x[(size_t)c0 * OUT_FEAT + fo];
        acc.x = fmaf(w0, v0.x, acc.x); acc.y = fmaf(w0, v0.y, acc.y);
        acc.z = fmaf(w0, v0.z, acc.z); acc.w = fmaf(w0, v0.w, acc.w);
    }

    acc.x = multispike(acc.x);
    acc.y = multispike(acc.y);
    acc.z = multispike(acc.z);
    acc.w = multispike(acc.w);
    *(float4*)&out[(size_t)warp * OUT_FEAT + fo] = acc;
}

// ---------------------------------------------------------------------------
extern "C" void kernel_launch(void* const* d_in, const int* in_sizes, int n_in,
                              void* d_out, int out_size) {
    const float* feat   = (const float*)d_in[0];
    const float* weight = (const float*)d_in[1];
    const int*   rows   = (const int*)d_in[2];
    const int*   cols   = (const int*)d_in[3];
    const float* ew     = (const float*)d_in[4];
    float* out = (float*)d_out;

    prep_kernel<<<(N_EDGES / 4 + 256) / 256, 256>>>(rows, weight);
    gemm_mma_kernel<<<(N_NODES + BM - 1) / BM, 128>>>(feat);
    spmm_kernel<<<(N_NODES * 32 + 255) / 256, 256>>>(cols, ew, out);
}